// round 1
// baseline (speedup 1.0000x reference)
#include <cuda_runtime.h>
#include <math_constants.h>
#include <cstdint>

#define MROWS 200
#define NCOLS 6
#define TOT   1200   // MROWS*NCOLS
#define KSEL  25
#define DIN   784
#define BMAX  16384

// ---------------- device scratch (static; no runtime allocation) ----------------
__device__ float g_WbT[TOT * TOT];          // Wb transposed: column c of Wb = row c of WbT
__device__ float g_ZA[BMAX * MROWS];        // precomputed Wa@x_t + ba
__device__ float g_Ymax[BMAX * MROWS];      // recorded y.max(axis=1) per step

// ---------------- transpose Wb -> g_WbT ----------------
__global__ void transpose_wb(const float* __restrict__ Wb) {
    __shared__ float tile[32][33];
    int bx = blockIdx.x * 32, by = blockIdx.y * 32;
    int x = bx + threadIdx.x;   // column of Wb
    if (x < TOT) {
        for (int dy = 0; dy < 32; dy += 8) {
            int yy = by + threadIdx.y + dy;      // row of Wb
            if (yy < TOT) tile[threadIdx.y + dy][threadIdx.x] = Wb[(size_t)yy * TOT + x];
        }
    }
    __syncthreads();
    int r = by + threadIdx.x;   // row of Wb = column index inside WbT row
    if (r < TOT) {
        for (int dy = 0; dy < 32; dy += 8) {
            int c = bx + threadIdx.y + dy;       // column of Wb = row of WbT
            if (c < TOT) g_WbT[(size_t)c * TOT + r] = tile[threadIdx.x][threadIdx.y + dy];
        }
    }
}

// ---------------- generic C[M,N] = A[M,K] @ B[N,K]^T + bias[N] ----------------
// block 256 threads, 64x64 tile, 4x4 microtile, K chunks of 16
__global__ void gemm_abt_kernel(const float* __restrict__ A, const float* __restrict__ Bw,
                                const float* __restrict__ bias, float* __restrict__ C,
                                int Mdim, int Ndim, int Kdim)
{
    const int TK = 16;
    __shared__ float As[TK][64 + 4];
    __shared__ float Bs[TK][64 + 4];
    const int m0 = blockIdx.x * 64;
    const int n0 = blockIdx.y * 64;
    const int tid = threadIdx.x;
    const int tx = tid & 15, ty = tid >> 4;
    float acc[4][4] = {};
    for (int k0 = 0; k0 < Kdim; k0 += TK) {
#pragma unroll
        for (int e = 0; e < 4; e++) {
            int lin = tid + e * 256;
            int r = lin / TK, k = lin % TK;
            float va = 0.f, vb = 0.f;
            if (k0 + k < Kdim) {
                if (m0 + r < Mdim) va = A[(size_t)(m0 + r) * Kdim + k0 + k];
                if (n0 + r < Ndim) vb = Bw[(size_t)(n0 + r) * Kdim + k0 + k];
            }
            As[k][r] = va;
            Bs[k][r] = vb;
        }
        __syncthreads();
#pragma unroll
        for (int kk = 0; kk < TK; kk++) {
            float a[4], b[4];
#pragma unroll
            for (int i2 = 0; i2 < 4; i2++) a[i2] = As[kk][ty * 4 + i2];
#pragma unroll
            for (int j2 = 0; j2 < 4; j2++) b[j2] = Bs[kk][tx * 4 + j2];
#pragma unroll
            for (int i2 = 0; i2 < 4; i2++)
#pragma unroll
                for (int j2 = 0; j2 < 4; j2++)
                    acc[i2][j2] = fmaf(a[i2], b[j2], acc[i2][j2]);
        }
        __syncthreads();
    }
#pragma unroll
    for (int i2 = 0; i2 < 4; i2++) {
        int m = m0 + ty * 4 + i2;
        if (m >= Mdim) continue;
#pragma unroll
        for (int j2 = 0; j2 < 4; j2++) {
            int n = n0 + tx * 4 + j2;
            if (n < Ndim) C[(size_t)m * Ndim + n] = acc[i2][j2] + bias[n];
        }
    }
}

// ---------------- the sequential scan: single persistent CTA ----------------
__global__ void __launch_bounds__(1024, 1)
scan_kernel(const float* __restrict__ bb, float* __restrict__ tail, int B)
{
    __shared__ __align__(16) float u[TOT];     // Wb @ psi (un-normalized recurrent drive)
    __shared__ float phi[TOT];
    __shared__ float psi[TOT];
    __shared__ float sig[TOT];
    __shared__ float ynew[TOT];                // sparse y scatter buffer (kept zeroed)
    __shared__ float bbs[TOT];
    __shared__ float za_s[2][MROWS];
    __shared__ float lam[MROWS];
    __shared__ __align__(16) int keys[MROWS];  // float bits of lam (all >0 -> int-order == float-order)
    __shared__ unsigned char jst[MROWS];
    __shared__ float red[32];
    __shared__ float s_smin, s_invalpha;
    __shared__ int   sel_p[64];
    __shared__ float sel_d[64];
    __shared__ int   n_sel;

    const int tid = threadIdx.x;
    const int T = 1024;

    for (int p = tid; p < TOT; p += T) {
        u[p] = 0.f; phi[p] = 0.f; psi[p] = 0.f; ynew[p] = 0.f; bbs[p] = bb[p];
    }
    if (tid < MROWS) za_s[0][tid] = g_ZA[tid];
    if (tid == 0) s_invalpha = 1.0f;           // initial x_b == 0 (u==0 anyway)
    __syncthreads();

    for (int t = 0; t < B; t++) {
        const int buf = t & 1;
        // ---- Phase A: sigma = z_a + u/alpha + bb, plus global min ----
        float lmin = CUDART_INF_F;
        const float inva = s_invalpha;
        for (int p = tid; p < TOT; p += T) {
            float v = za_s[buf][p / 6] + fmaf(u[p], inva, bbs[p]);
            sig[p] = v;
            lmin = fminf(lmin, v);
        }
#pragma unroll
        for (int o = 16; o; o >>= 1) lmin = fminf(lmin, __shfl_xor_sync(0xffffffffu, lmin, o));
        if ((tid & 31) == 0) red[tid >> 5] = lmin;
        __syncthreads();                                   // S1
        if (tid < 32) {
            float v = red[tid];
#pragma unroll
            for (int o = 16; o; o >>= 1) v = fminf(v, __shfl_xor_sync(0xffffffffu, v, o));
            if (tid == 0) s_smin = v;
        }
        if (tid == T - 1) n_sel = 0;
        __syncthreads();                                   // S2
        const float smin = s_smin;

        // ---- Phase B: per-row argmax of pi (first-index on ties, like jnp.argmax) ----
        if (tid < MROWS) {
            const int i = tid;
            float best = -CUDART_INF_F; int bj = 0;
#pragma unroll
            for (int j = 0; j < 6; j++) {
                float pv = (1.0f - phi[i * 6 + j]) * (sig[i * 6 + j] - smin + 1.0f);
                if (pv > best) { best = pv; bj = j; }
            }
            lam[i] = best; jst[i] = (unsigned char)bj;
            keys[i] = __float_as_int(best);                // lam > 0 always
        } else if (tid >= 256 && tid < 256 + MROWS) {
            int i2 = tid - 256;                            // prefetch next z_a row
            if (t + 1 < B) za_s[buf ^ 1][i2] = g_ZA[(size_t)(t + 1) * MROWS + i2];
        }
        __syncthreads();                                   // S3

        // ---- Phase C: top-25 selection via rank counting (fast strict pass) ----
        if (tid < MROWS) {
            const int i = tid;
            const int ki = keys[i];
            int cnt = 0;
            const int4* k4 = (const int4*)keys;
#pragma unroll 10
            for (int j4 = 0; j4 < MROWS / 4; j4++) {
                int4 kk = k4[j4];
                cnt += (kk.x > ki) + (kk.y > ki) + (kk.z > ki) + (kk.w > ki);
            }
            float ym = 0.0f;
            if (cnt < KSEL) {
                int p = i * 6 + (int)jst[i];
                float yv = tanhf(sig[p]);
                ym = fmaxf(yv, 0.0f);
                int slot = atomicAdd(&n_sel, 1);
                if (slot < 64) { sel_p[slot] = p; sel_d[slot] = yv - 0.5f * psi[p]; }
                ynew[p] = yv;
            }
            g_Ymax[(size_t)t * MROWS + i] = ym;
        }
        __syncthreads();                                   // S4

        // ---- Rare exact-tie fallback (selected count != 25) ----
        if (n_sel != KSEL) {
            for (int p = tid; p < TOT; p += T) ynew[p] = 0.0f;
            __syncthreads();
            if (tid == 0) n_sel = 0;
            __syncthreads();
            if (tid < MROWS) {
                const int i = tid;
                const int ki = keys[i];
                int cnt = 0;
                for (int j = 0; j < MROWS; j++) {
                    int kj = keys[j];
                    cnt += (kj > ki) || (kj == ki && j < i);  // lax.top_k tie rule
                }
                float ym = 0.0f;
                if (cnt < KSEL) {
                    int p = i * 6 + (int)jst[i];
                    float yv = tanhf(sig[p]);
                    ym = fmaxf(yv, 0.0f);
                    int slot = atomicAdd(&n_sel, 1);
                    sel_p[slot] = p; sel_d[slot] = yv - 0.5f * psi[p];
                    ynew[p] = yv;
                }
                g_Ymax[(size_t)t * MROWS + i] = ym;
            }
            __syncthreads();
        }

        // ---- Phase D (overlapped): warps 0-9 update u; warps 10-31 update psi/phi + alpha ----
        if (tid < 320) {
            if (tid < TOT / 4) {
                float4* u4 = (float4*)u;
                float4 acc = u4[tid];
                acc.x *= 0.5f; acc.y *= 0.5f; acc.z *= 0.5f; acc.w *= 0.5f;
                const int ns = n_sel;
                for (int k = 0; k < ns; k++) {
                    float d = sel_d[k];
                    if (d > 0.0f) {
                        const float4* w4 = (const float4*)(g_WbT + (size_t)sel_p[k] * TOT);
                        float4 w = __ldg(&w4[tid]);
                        acc.x = fmaf(d, w.x, acc.x);
                        acc.y = fmaf(d, w.y, acc.y);
                        acc.z = fmaf(d, w.z, acc.z);
                        acc.w = fmaf(d, w.w, acc.w);
                    }
                }
                u4[tid] = acc;
            }
        } else {
            float part = 0.0f;
            for (int p = tid - 320; p < TOT; p += T - 320) {
                float nv = ynew[p];
                float ps = fmaxf(0.5f * psi[p], nv);
                psi[p] = ps;
                phi[p] = fmaxf(0.5f * phi[p], nv);
                ynew[p] = 0.0f;
                part += ps;
            }
#pragma unroll
            for (int o = 16; o; o >>= 1) part += __shfl_xor_sync(0xffffffffu, part, o);
            if ((tid & 31) == 0) red[tid >> 5] = part;
        }
        __syncthreads();                                   // S5
        if (tid < 32) {
            float v = (tid >= 10) ? red[tid] : 0.0f;
#pragma unroll
            for (int o = 16; o; o >>= 1) v += __shfl_xor_sync(0xffffffffu, v, o);
            if (tid == 0) {
                float a = (v == 0.0f) ? 1.0f : v;
                s_invalpha = 1.0f / a;
            }
        }
        __syncthreads();                                   // S6
    }

    // final carry outputs: x_b = psi/alpha, phi, psi
    const float inva = s_invalpha;
    for (int p = tid; p < TOT; p += T) {
        tail[p]            = psi[p] * inva;
        tail[TOT + p]      = phi[p];
        tail[2 * TOT + p]  = psi[p];
    }
}

// ---------------- launch ----------------
extern "C" void kernel_launch(void* const* d_in, const int* in_sizes, int n_in,
                              void* d_out, int out_size)
{
    const float* batch_x = (const float*)d_in[0];   // (B, 784)
    const float* Wa      = (const float*)d_in[1];   // (200, 784)
    const float* ba      = (const float*)d_in[2];   // (200,)
    const float* Wb      = (const float*)d_in[3];   // (1200, 1200)
    const float* bb      = (const float*)d_in[4];   // (1200,)
    const float* Wd      = (const float*)d_in[5];   // (784, 200)
    const float* bd      = (const float*)d_in[6];   // (784,)
    float* out = (float*)d_out;

    const int B = in_sizes[0] / DIN;

    float *pZA = nullptr, *pYmax = nullptr;
    cudaGetSymbolAddress((void**)&pZA, g_ZA);
    cudaGetSymbolAddress((void**)&pYmax, g_Ymax);

    // 1) Wb transpose for coalesced column gathers
    {
        dim3 tb(32, 8);
        dim3 tg((TOT + 31) / 32, (TOT + 31) / 32);
        transpose_wb<<<tg, tb>>>(Wb);
    }
    // 2) hoisted input GEMM: ZA[t][i] = Wa[i,:] . x_t + ba[i]
    {
        dim3 grid((B + 63) / 64, (MROWS + 63) / 64);
        gemm_abt_kernel<<<grid, 256>>>(batch_x, Wa, ba, pZA, B, MROWS, DIN);
    }
    // 3) sequential scan (records Ymax, writes carry tail)
    scan_kernel<<<1, 1024>>>(bb, out + (size_t)B * DIN, B);
    // 4) deferred output GEMM: preds[t][d] = Wd[d,:] . ymax_t + bd[d]
    {
        dim3 grid((B + 63) / 64, (DIN + 63) / 64);
        gemm_abt_kernel<<<grid, 256>>>(pYmax, Wd, bd, out, B, DIN, MROWS);
    }
}